// round 2
// baseline (speedup 1.0000x reference)
#include <cuda_runtime.h>
#include <cuda_bf16.h>
#include <math.h>
#include <stdint.h>

// ---------------------------------------------------------------------------
// MPWEncoder: y = tanh(conv2(tanh(conv1(tanh(tanh(x @ (Wih*Mih)^T + bih) @
//                  (Whc*Mhc)^T + bhc)))))
// Dims: BATCH=16384, IN=4096, HID=2048, CNV1=1024, out = [16384, 256]
// ---------------------------------------------------------------------------

#define BATCH   16384
#define IN_DIM  4096
#define HID_DIM 2048
#define CNV_DIM 1024
#define OUT_DIM 256   // CNV_DIM / 4

// __device__ global scratch (no allocations allowed)
__device__ __align__(128) float g_w1t[IN_DIM  * HID_DIM];  // [K=4096][N=2048]
__device__ __align__(128) float g_w2t[HID_DIM * CNV_DIM];  // [K=2048][N=1024]
__device__ __align__(128) float g_h  [(size_t)BATCH * HID_DIM];
__device__ __align__(128) float g_c  [(size_t)BATCH * CNV_DIM];
__device__ int g_mask_mode[2];   // 0 = uint8, 1 = int32, 2 = float32

// ---------------------------------------------------------------------------
// Detect how the harness materialized the jnp.bool_ masks.
// Scans 256 32-bit words:
//   float32 bools -> words are 0 or 0x3F800000
//   int32 bools   -> words are exactly 0 or 1
//   uint8 bools   -> packed bytes; words like 0x01000100 (>1, !=0x3F800000)
// ---------------------------------------------------------------------------
__global__ void detect_mask_mode(const uint32_t* __restrict__ m, int* __restrict__ mode) {
    int floatish = 0, all01 = 1;
    for (int i = 0; i < 256; ++i) {
        uint32_t w = m[i];
        if (w == 0x3F800000u) floatish = 1;
        if (w > 1u) all01 = 0;
    }
    *mode = floatish ? 2 : (all01 ? 1 : 0);
}

// ---------------------------------------------------------------------------
// Prep: wt[k][n] = w[n][k] * (mask[n][k] != 0)   (smem-tiled transpose)
// w: [N, K] row-major, wt: [K, N] row-major
// ---------------------------------------------------------------------------
__global__ void prep_masked_wt(const float* __restrict__ w,
                               const void* __restrict__ mask,
                               const int* __restrict__ mode_p,
                               float* __restrict__ wt, int N, int K) {
    __shared__ float tile[32][33];
    const int mode = *mode_p;
    int n0 = blockIdx.y * 32;
    int k0 = blockIdx.x * 32;
    int n = n0 + threadIdx.y;
    int k = k0 + threadIdx.x;
    size_t src = (size_t)n * K + k;

    bool mb;
    if (mode == 0)      mb = ((const uint8_t*)mask)[src] != 0;
    else if (mode == 1) mb = ((const int*)mask)[src] != 0;
    else                mb = ((const float*)mask)[src] != 0.0f;

    tile[threadIdx.y][threadIdx.x] = mb ? w[src] : 0.0f;
    __syncthreads();
    // write wt[k0+ty][n0+tx] = masked w[n0+tx][k0+ty]
    wt[(size_t)(k0 + threadIdx.y) * N + (n0 + threadIdx.x)] =
        tile[threadIdx.x][threadIdx.y];
}

// ---------------------------------------------------------------------------
// Fused GEMM + bias + tanh:  C[M,N] = tanh(A[M,K] @ B[K,N] + bias[N])
// Tiles: BM=BN=128, BK=8. 256 threads, 8x8 microtile per thread.
// All dims here are multiples of the tile sizes -> no bounds checks.
// ---------------------------------------------------------------------------
#define BM 128
#define BN 128
#define BK 8
#define TM 8
#define TN 8

__global__ __launch_bounds__(256, 2)
void gemm_bias_tanh(const float* __restrict__ A, const float* __restrict__ B,
                    const float* __restrict__ bias, float* __restrict__ C,
                    int M, int N, int K) {
    __shared__ float As[BK][BM];   // transposed A tile
    __shared__ float Bs[BK][BN];

    const int tid = threadIdx.x;
    const int m0 = blockIdx.y * BM;
    const int n0 = blockIdx.x * BN;

    // global-load assignments (one float4 of A, one float4 of B per thread)
    const int arow = tid >> 1;          // 0..127
    const int acol = (tid & 1) * 4;     // 0 or 4
    const int brow = tid >> 5;          // 0..7
    const int bcol = (tid & 31) * 4;    // 0..124

    const float* Aptr = A + (size_t)(m0 + arow) * K + acol;
    const float* Bptr = B + (size_t)brow * N + n0 + bcol;

    float4 aReg = *(const float4*)Aptr;
    float4 bReg = *(const float4*)Bptr;

    const int ty = tid >> 4;            // 0..15 -> row group
    const int tx = tid & 15;            // 0..15 -> col group

    float acc[TM][TN];
#pragma unroll
    for (int i = 0; i < TM; ++i)
#pragma unroll
        for (int j = 0; j < TN; ++j) acc[i][j] = 0.0f;

    const int nTiles = K / BK;
    for (int t = 0; t < nTiles; ++t) {
        As[acol + 0][arow] = aReg.x;
        As[acol + 1][arow] = aReg.y;
        As[acol + 2][arow] = aReg.z;
        As[acol + 3][arow] = aReg.w;
        *(float4*)&Bs[brow][bcol] = bReg;
        __syncthreads();

        if (t + 1 < nTiles) {           // prefetch next K-slab into registers
            aReg = *(const float4*)(Aptr + (size_t)(t + 1) * BK);
            bReg = *(const float4*)(Bptr + (size_t)(t + 1) * BK * N);
        }

#pragma unroll
        for (int k = 0; k < BK; ++k) {
            float af[TM], bf[TN];
#pragma unroll
            for (int i = 0; i < TM; ++i) af[i] = As[k][ty * TM + i];
#pragma unroll
            for (int j = 0; j < TN; ++j) bf[j] = Bs[k][tx * TN + j];
#pragma unroll
            for (int i = 0; i < TM; ++i)
#pragma unroll
                for (int j = 0; j < TN; ++j)
                    acc[i][j] = fmaf(af[i], bf[j], acc[i][j]);
        }
        __syncthreads();
    }

    // epilogue: bias + tanh
#pragma unroll
    for (int i = 0; i < TM; ++i) {
        const int row = m0 + ty * TM + i;
        float* Crow = C + (size_t)row * N + n0 + tx * TN;
#pragma unroll
        for (int j = 0; j < TN; ++j) {
            Crow[j] = tanhf(acc[i][j] + bias[n0 + tx * TN + j]);
        }
    }
}

// ---------------------------------------------------------------------------
// Fused conv1d(k=2,s=2)+tanh  x2:
// out[b][j] = tanh(w2.x*tanh(w1.x*c[4j]+w1.y*c[4j+1]+b1)
//                + w2.y*tanh(w1.x*c[4j+2]+w1.y*c[4j+3]+b1) + b2)
// ---------------------------------------------------------------------------
__global__ void conv_fused(const float* __restrict__ c,
                           const float* __restrict__ wc1, const float* __restrict__ bc1,
                           const float* __restrict__ wc2, const float* __restrict__ bc2,
                           float* __restrict__ out) {
    int idx = blockIdx.x * blockDim.x + threadIdx.x;   // over BATCH*OUT_DIM
    if (idx >= BATCH * OUT_DIM) return;
    const float w10 = wc1[0], w11 = wc1[1];
    const float w20 = wc2[0], w21 = wc2[1];
    const float b1 = bc1[0], b2 = bc2[0];
    float4 v = ((const float4*)c)[idx];   // c row = 1024 floats = 256 float4; flat idx works
    float t1 = tanhf(fmaf(v.x, w10, fmaf(v.y, w11, b1)));
    float t2 = tanhf(fmaf(v.z, w10, fmaf(v.w, w11, b1)));
    out[idx] = tanhf(fmaf(t1, w20, fmaf(t2, w21, b2)));
}

// ---------------------------------------------------------------------------
// kernel_launch
// Input order: 0 x, 1 mask_ih, 2 mask_hc, 3 w_ih, 4 b_ih, 5 w_hc, 6 b_hc,
//              7 w_c1, 8 b_c1, 9 w_c2, 10 b_c2
// ---------------------------------------------------------------------------
extern "C" void kernel_launch(void* const* d_in, const int* in_sizes, int n_in,
                              void* d_out, int out_size) {
    const float* x       = (const float*)d_in[0];
    const void*  mask_ih = d_in[1];
    const void*  mask_hc = d_in[2];
    const float* w_ih    = (const float*)d_in[3];
    const float* b_ih    = (const float*)d_in[4];
    const float* w_hc    = (const float*)d_in[5];
    const float* b_hc    = (const float*)d_in[6];
    const float* w_c1    = (const float*)d_in[7];
    const float* b_c1    = (const float*)d_in[8];
    const float* w_c2    = (const float*)d_in[9];
    const float* b_c2    = (const float*)d_in[10];
    float* out = (float*)d_out;

    float* w1t; cudaGetSymbolAddress((void**)&w1t, g_w1t);
    float* w2t; cudaGetSymbolAddress((void**)&w2t, g_w2t);
    float* h;   cudaGetSymbolAddress((void**)&h,   g_h);
    float* c;   cudaGetSymbolAddress((void**)&c,   g_c);
    int* mode;  cudaGetSymbolAddress((void**)&mode, g_mask_mode);

    // 0) detect mask dtype (bool_ may arrive as uint8 / int32 / float32)
    detect_mask_mode<<<1, 1>>>((const uint32_t*)mask_ih, mode + 0);
    detect_mask_mode<<<1, 1>>>((const uint32_t*)mask_hc, mode + 1);

    // 1) masked + transposed weights
    {
        dim3 thr(32, 32);
        dim3 g1(IN_DIM / 32, HID_DIM / 32);    // w_ih: [2048, 4096]
        prep_masked_wt<<<g1, thr>>>(w_ih, mask_ih, mode + 0, w1t, HID_DIM, IN_DIM);
        dim3 g2(HID_DIM / 32, CNV_DIM / 32);   // w_hc: [1024, 2048]
        prep_masked_wt<<<g2, thr>>>(w_hc, mask_hc, mode + 1, w2t, CNV_DIM, HID_DIM);
    }

    // 2) h = tanh(x @ w1t + b_ih)    [16384, 2048]
    {
        dim3 grid(HID_DIM / BN, BATCH / BM);   // (16, 128)
        gemm_bias_tanh<<<grid, 256>>>(x, w1t, b_ih, h, BATCH, HID_DIM, IN_DIM);
    }

    // 3) c = tanh(h @ w2t + b_hc)    [16384, 1024]
    {
        dim3 grid(CNV_DIM / BN, BATCH / BM);   // (8, 128)
        gemm_bias_tanh<<<grid, 256>>>(h, w2t, b_hc, c, BATCH, CNV_DIM, HID_DIM);
    }

    // 4) fused double conv1d(k2,s2) + tanh    [16384, 256]
    {
        int total = BATCH * OUT_DIM;
        conv_fused<<<(total + 255) / 256, 256>>>(c, w_c1, b_c1, w_c2, b_c2, out);
    }
}

// round 5
// speedup vs baseline: 2.1969x; 2.1969x over previous
#include <cuda_runtime.h>
#include <cuda_bf16.h>
#include <math.h>
#include <stdint.h>

// ---------------------------------------------------------------------------
// MPWEncoder via mma.sync (bf16-split x3 emulated fp32) — sm_103-safe PTX.
// Dims: BATCH=16384, IN=4096, HID=2048, CNV1=1024, out [16384, 256]
// ---------------------------------------------------------------------------
#define BATCH   16384
#define IN_DIM  4096
#define HID_DIM 2048
#define CNV_DIM 1024
#define OUT_DIM 256

typedef __nv_bfloat16 bf16;

// ------------------------- device scratch (no allocs) ----------------------
__device__ __align__(1024) bf16 g_x_hi [(size_t)BATCH * IN_DIM];
__device__ __align__(1024) bf16 g_x_lo [(size_t)BATCH * IN_DIM];
__device__ __align__(1024) bf16 g_w1_hi[(size_t)HID_DIM * IN_DIM];
__device__ __align__(1024) bf16 g_w1_lo[(size_t)HID_DIM * IN_DIM];
__device__ __align__(1024) bf16 g_h_hi [(size_t)BATCH * HID_DIM];
__device__ __align__(1024) bf16 g_h_lo [(size_t)BATCH * HID_DIM];
__device__ __align__(1024) bf16 g_w2_hi[(size_t)CNV_DIM * HID_DIM];
__device__ __align__(1024) bf16 g_w2_lo[(size_t)CNV_DIM * HID_DIM];
__device__ __align__(1024) float g_c   [(size_t)BATCH * CNV_DIM];
__device__ int g_mask_mode[2];

// ------------------------- PTX helpers -------------------------------------
__device__ __forceinline__ uint32_t smem_u32(const void* p) {
    uint32_t a;
    asm("{ .reg .u64 t; cvta.to.shared.u64 t, %1; cvt.u32.u64 %0, t; }"
        : "=r"(a) : "l"(p));
    return a;
}
__device__ __forceinline__ void cp16(uint32_t dst, const void* src) {
    asm volatile("cp.async.cg.shared.global [%0], [%1], 16;" :: "r"(dst), "l"(src));
}
__device__ __forceinline__ void cp_commit() {
    asm volatile("cp.async.commit_group;" ::: "memory");
}
template <int N>
__device__ __forceinline__ void cp_wait() {
    asm volatile("cp.async.wait_group %0;" :: "n"(N) : "memory");
}
__device__ __forceinline__ void ldsm_x4(uint32_t addr, uint32_t* r) {
    asm volatile("ldmatrix.sync.aligned.m8n8.x4.shared.b16 {%0,%1,%2,%3}, [%4];"
                 : "=r"(r[0]), "=r"(r[1]), "=r"(r[2]), "=r"(r[3]) : "r"(addr));
}
__device__ __forceinline__ void mma16816(float* c, const uint32_t* a, const uint32_t* b) {
    asm volatile(
        "mma.sync.aligned.m16n8k16.row.col.f32.bf16.bf16.f32 "
        "{%0,%1,%2,%3}, {%4,%5,%6,%7}, {%8,%9}, {%0,%1,%2,%3};"
        : "+f"(c[0]), "+f"(c[1]), "+f"(c[2]), "+f"(c[3])
        : "r"(a[0]), "r"(a[1]), "r"(a[2]), "r"(a[3]), "r"(b[0]), "r"(b[1]));
}

// ------------------------- mask detection + split preps ---------------------
__global__ void detect_mask_mode(const uint32_t* __restrict__ m, int* __restrict__ mode) {
    int floatish = 0, all01 = 1;
    for (int i = 0; i < 256; ++i) {
        uint32_t w = m[i];
        if (w == 0x3F800000u) floatish = 1;
        if (w > 1u) all01 = 0;
    }
    *mode = floatish ? 2 : (all01 ? 1 : 0);
}

__device__ __forceinline__ uint32_t pack_bf2(float a, float b) {
    __nv_bfloat162 t = __floats2bfloat162_rn(a, b);
    return *reinterpret_cast<uint32_t*>(&t);
}
__device__ __forceinline__ void split4(float4 v, uint2& ho, uint2& lo) {
    float h0 = __bfloat162float(__float2bfloat16(v.x));
    float h1 = __bfloat162float(__float2bfloat16(v.y));
    float h2 = __bfloat162float(__float2bfloat16(v.z));
    float h3 = __bfloat162float(__float2bfloat16(v.w));
    ho.x = pack_bf2(h0, h1);
    ho.y = pack_bf2(h2, h3);
    lo.x = pack_bf2(v.x - h0, v.y - h1);
    lo.y = pack_bf2(v.z - h2, v.w - h3);
}

__global__ void prep_split_x(const float* __restrict__ x,
                             bf16* __restrict__ hi, bf16* __restrict__ lo, size_t n4) {
    size_t i = (size_t)blockIdx.x * blockDim.x + threadIdx.x;
    if (i >= n4) return;
    float4 v = ((const float4*)x)[i];
    uint2 ho, lv;
    split4(v, ho, lv);
    ((uint2*)hi)[i] = ho;
    ((uint2*)lo)[i] = lv;
}

__global__ void prep_split_w(const float* __restrict__ w, const void* __restrict__ mask,
                             const int* __restrict__ mode_p,
                             bf16* __restrict__ hi, bf16* __restrict__ lo, size_t n4) {
    size_t i = (size_t)blockIdx.x * blockDim.x + threadIdx.x;
    if (i >= n4) return;
    const int mode = *mode_p;
    float4 v = ((const float4*)w)[i];
    bool m0, m1, m2, m3;
    if (mode == 0) {
        uchar4 mm = ((const uchar4*)mask)[i];
        m0 = mm.x; m1 = mm.y; m2 = mm.z; m3 = mm.w;
    } else if (mode == 1) {
        int4 mm = ((const int4*)mask)[i];
        m0 = mm.x; m1 = mm.y; m2 = mm.z; m3 = mm.w;
    } else {
        float4 mm = ((const float4*)mask)[i];
        m0 = mm.x != 0.f; m1 = mm.y != 0.f; m2 = mm.z != 0.f; m3 = mm.w != 0.f;
    }
    v.x = m0 ? v.x : 0.f; v.y = m1 ? v.y : 0.f;
    v.z = m2 ? v.z : 0.f; v.w = m3 ? v.w : 0.f;
    uint2 ho, lv;
    split4(v, ho, lv);
    ((uint2*)hi)[i] = ho;
    ((uint2*)lo)[i] = lv;
}

// ------------------------- mma.sync GEMM ------------------------------------
// C[M,N] = tanh(A[M,K] @ B[N,K]^T + bias[N]); A/B as bf16 hi/lo pairs.
// acc += Ah*Bh + Ah*Bl + Al*Bh  (fp32 register accumulators)
// Block tile 256x128x32, 8 warps (warp tile 64x64), 2-stage cp.async pipeline.
// NOTE: B is [n][k] row-major == column-major B operand, so ldmatrix is the
// NON-trans variant (trans here double-transposes and scrambles the operand).
#define BMT 256
#define BNT 128
#define BKT 32
#define ROWB 80                          // 64B data + 16B pad per K-slab row
#define A_BYTES (BMT * ROWB)             // 20480
#define B_BYTES (BNT * ROWB)             // 10240
#define STAGE_BYTES (2 * A_BYTES + 2 * B_BYTES)   // 61440
#define SMEM_GEMM (2 * STAGE_BYTES)      // 122880

__device__ __forceinline__ void load_stage(uint32_t sb,
                                           const bf16* Ah, const bf16* Al,
                                           const bf16* Bh, const bf16* Bl,
                                           int m0, int n0, int k0, int K, int tid) {
#pragma unroll
    for (int i = 0; i < 4; ++i) {
        const int ch = tid + (i << 8);
        const int row = ch >> 2, u = ch & 3;
        const uint32_t doff = row * ROWB + ((u ^ (row & 3)) << 4);
        const size_t g = (size_t)(m0 + row) * K + k0 + u * 8;
        cp16(sb + doff, Ah + g);
        cp16(sb + A_BYTES + doff, Al + g);
    }
#pragma unroll
    for (int i = 0; i < 2; ++i) {
        const int ch = tid + (i << 8);
        const int row = ch >> 2, u = ch & 3;
        const uint32_t doff = row * ROWB + ((u ^ (row & 3)) << 4);
        const size_t g = (size_t)(n0 + row) * K + k0 + u * 8;
        cp16(sb + 2 * A_BYTES + doff, Bh + g);
        cp16(sb + 2 * A_BYTES + B_BYTES + doff, Bl + g);
    }
}

template <int MODE>   // 0: bf16 hi/lo out; 1: fp32 out
__global__ __launch_bounds__(256, 1)
void gemm_mma(const bf16* __restrict__ Ah, const bf16* __restrict__ Al,
              const bf16* __restrict__ Bh, const bf16* __restrict__ Bl,
              const float* __restrict__ bias,
              bf16* __restrict__ Ch, bf16* __restrict__ Cl, float* __restrict__ Cf,
              int M, int N, int K) {
    extern __shared__ __align__(128) char smem[];
    const uint32_t sbase = smem_u32(smem);
    const int tid = threadIdx.x;
    const int wid = tid >> 5;
    const int lane = tid & 31;
    const int warp_m = wid >> 1;         // 0..3 -> 64-row slice
    const int warp_n = wid & 1;          // 0..1 -> 64-col slice
    const int m0 = blockIdx.y * BMT;
    const int n0 = blockIdx.x * BNT;

    float acc[4][8][4];
#pragma unroll
    for (int a = 0; a < 4; ++a)
#pragma unroll
        for (int b = 0; b < 8; ++b)
#pragma unroll
            for (int d = 0; d < 4; ++d) acc[a][b][d] = 0.0f;

    // per-lane constant pieces of ldmatrix addressing
    const int aRow = warp_m * 64 + (lane & 7) + (((lane >> 3) & 1) << 3);
    const int aUsel = lane >> 4;              // 0/1 -> k-chunk within 16-wide step
    const int bRow = warp_n * 64 + ((lane >> 4) << 3) + (lane & 7);
    const int bUsel = (lane >> 3) & 1;        // 0/1

    const int T = K / BKT;
    load_stage(sbase, Ah, Al, Bh, Bl, m0, n0, 0, K, tid);
    cp_commit();

    for (int t = 0; t < T; ++t) {
        if (t + 1 < T) {
            load_stage(sbase + ((t + 1) & 1) * STAGE_BYTES, Ah, Al, Bh, Bl,
                       m0, n0, (t + 1) * BKT, K, tid);
            cp_commit();
            cp_wait<1>();
        } else {
            cp_wait<0>();
        }
        __syncthreads();

        const uint32_t stg = sbase + (t & 1) * STAGE_BYTES;
        const uint32_t aHiB = stg, aLoB = stg + A_BYTES;
        const uint32_t bHiB = stg + 2 * A_BYTES, bLoB = bHiB + B_BYTES;

#pragma unroll
        for (int kk = 0; kk < 2; ++kk) {
            uint32_t ah[4][4], al[4][4];
#pragma unroll
            for (int mf = 0; mf < 4; ++mf) {
                const int m = aRow + mf * 16;
                const int u = kk * 2 + aUsel;
                const uint32_t off = m * ROWB + ((u ^ (m & 3)) << 4);
                ldsm_x4(aHiB + off, ah[mf]);
                ldsm_x4(aLoB + off, al[mf]);
            }
#pragma unroll
            for (int nfp = 0; nfp < 4; ++nfp) {
                const int n = bRow + nfp * 16;
                const int u = kk * 2 + bUsel;
                const uint32_t off = n * ROWB + ((u ^ (n & 3)) << 4);
                uint32_t bh[4], bl[4];
                ldsm_x4(bHiB + off, bh);   // NON-trans: [n][k] tile is already col-major B
                ldsm_x4(bLoB + off, bl);
#pragma unroll
                for (int mf = 0; mf < 4; ++mf) {
                    mma16816(acc[mf][2 * nfp],     ah[mf], bh);
                    mma16816(acc[mf][2 * nfp],     ah[mf], bl);
                    mma16816(acc[mf][2 * nfp],     al[mf], bh);
                    mma16816(acc[mf][2 * nfp + 1], ah[mf], bh + 2);
                    mma16816(acc[mf][2 * nfp + 1], ah[mf], bl + 2);
                    mma16816(acc[mf][2 * nfp + 1], al[mf], bh + 2);
                }
            }
        }
        __syncthreads();
    }

    // ----------------- epilogue: bias + tanh + store -----------------------
    const int gid = lane >> 2, tg = lane & 3;
#pragma unroll
    for (int mf = 0; mf < 4; ++mf) {
#pragma unroll
        for (int nf = 0; nf < 8; ++nf) {
            const int row0 = m0 + warp_m * 64 + mf * 16 + gid;
            const int col = n0 + warp_n * 64 + nf * 8 + tg * 2;
            const float bv0 = bias[col], bv1 = bias[col + 1];
            const float* a4 = acc[mf][nf];
            const float v00 = tanhf(a4[0] + bv0);
            const float v01 = tanhf(a4[1] + bv1);
            const float v10 = tanhf(a4[2] + bv0);
            const float v11 = tanhf(a4[3] + bv1);
            if (MODE == 0) {
                const float h00 = __bfloat162float(__float2bfloat16(v00));
                const float h01 = __bfloat162float(__float2bfloat16(v01));
                const float h10 = __bfloat162float(__float2bfloat16(v10));
                const float h11 = __bfloat162float(__float2bfloat16(v11));
                uint32_t* ChW = (uint32_t*)Ch;
                uint32_t* ClW = (uint32_t*)Cl;
                const size_t w0 = (size_t)row0 * (N >> 1) + (col >> 1);
                const size_t w1 = (size_t)(row0 + 8) * (N >> 1) + (col >> 1);
                ChW[w0] = pack_bf2(h00, h01);
                ClW[w0] = pack_bf2(v00 - h00, v01 - h01);
                ChW[w1] = pack_bf2(h10, h11);
                ClW[w1] = pack_bf2(v10 - h10, v11 - h11);
            } else {
                float2* p0 = (float2*)(Cf + (size_t)row0 * N + col);
                float2* p1 = (float2*)(Cf + (size_t)(row0 + 8) * N + col);
                *p0 = make_float2(v00, v01);
                *p1 = make_float2(v10, v11);
            }
        }
    }
}

// ------------------------- fused double conv --------------------------------
__global__ void conv_fused(const float* __restrict__ c,
                           const float* __restrict__ wc1, const float* __restrict__ bc1,
                           const float* __restrict__ wc2, const float* __restrict__ bc2,
                           float* __restrict__ out) {
    int idx = blockIdx.x * blockDim.x + threadIdx.x;
    if (idx >= BATCH * OUT_DIM) return;
    const float w10 = wc1[0], w11 = wc1[1];
    const float w20 = wc2[0], w21 = wc2[1];
    const float b1 = bc1[0], b2 = bc2[0];
    float4 v = ((const float4*)c)[idx];
    float t1 = tanhf(fmaf(v.x, w10, fmaf(v.y, w11, b1)));
    float t2 = tanhf(fmaf(v.z, w10, fmaf(v.w, w11, b1)));
    out[idx] = tanhf(fmaf(t1, w20, fmaf(t2, w21, b2)));
}

// ------------------------- launch ------------------------------------------
extern "C" void kernel_launch(void* const* d_in, const int* in_sizes, int n_in,
                              void* d_out, int out_size) {
    const float* x       = (const float*)d_in[0];
    const void*  mask_ih = d_in[1];
    const void*  mask_hc = d_in[2];
    const float* w_ih    = (const float*)d_in[3];
    const float* b_ih    = (const float*)d_in[4];
    const float* w_hc    = (const float*)d_in[5];
    const float* b_hc    = (const float*)d_in[6];
    const float* w_c1    = (const float*)d_in[7];
    const float* b_c1    = (const float*)d_in[8];
    const float* w_c2    = (const float*)d_in[9];
    const float* b_c2    = (const float*)d_in[10];
    float* out = (float*)d_out;

    bf16 *x_hi, *x_lo, *w1_hi, *w1_lo, *h_hi, *h_lo, *w2_hi, *w2_lo;
    float* c;
    int* mode;
    cudaGetSymbolAddress((void**)&x_hi, g_x_hi);
    cudaGetSymbolAddress((void**)&x_lo, g_x_lo);
    cudaGetSymbolAddress((void**)&w1_hi, g_w1_hi);
    cudaGetSymbolAddress((void**)&w1_lo, g_w1_lo);
    cudaGetSymbolAddress((void**)&h_hi, g_h_hi);
    cudaGetSymbolAddress((void**)&h_lo, g_h_lo);
    cudaGetSymbolAddress((void**)&w2_hi, g_w2_hi);
    cudaGetSymbolAddress((void**)&w2_lo, g_w2_lo);
    cudaGetSymbolAddress((void**)&c, g_c);
    cudaGetSymbolAddress((void**)&mode, g_mask_mode);

    cudaFuncSetAttribute(gemm_mma<0>, cudaFuncAttributeMaxDynamicSharedMemorySize, SMEM_GEMM);
    cudaFuncSetAttribute(gemm_mma<1>, cudaFuncAttributeMaxDynamicSharedMemorySize, SMEM_GEMM);

    // 0) mask dtype detection
    detect_mask_mode<<<1, 1>>>((const uint32_t*)mask_ih, mode + 0);
    detect_mask_mode<<<1, 1>>>((const uint32_t*)mask_hc, mode + 1);

    // 1) hi/lo splits (x, masked w1, masked w2)
    {
        size_t n4 = (size_t)BATCH * IN_DIM / 4;
        prep_split_x<<<(unsigned)((n4 + 255) / 256), 256>>>(x, x_hi, x_lo, n4);
    }
    {
        size_t n4 = (size_t)HID_DIM * IN_DIM / 4;
        prep_split_w<<<(unsigned)((n4 + 255) / 256), 256>>>(w_ih, mask_ih, mode + 0,
                                                            w1_hi, w1_lo, n4);
    }
    {
        size_t n4 = (size_t)CNV_DIM * HID_DIM / 4;
        prep_split_w<<<(unsigned)((n4 + 255) / 256), 256>>>(w_hc, mask_hc, mode + 1,
                                                            w2_hi, w2_lo, n4);
    }

    // 2) h = tanh(x @ w1^T + b_ih) -> bf16 hi/lo
    {
        dim3 grid(HID_DIM / BNT, BATCH / BMT);   // (16, 64)
        gemm_mma<0><<<grid, 256, SMEM_GEMM>>>(x_hi, x_lo, w1_hi, w1_lo, b_ih,
                                              h_hi, h_lo, nullptr,
                                              BATCH, HID_DIM, IN_DIM);
    }

    // 3) c = tanh(h @ w2^T + b_hc) -> fp32
    {
        dim3 grid(CNV_DIM / BNT, BATCH / BMT);   // (8, 64)
        gemm_mma<1><<<grid, 256, SMEM_GEMM>>>(h_hi, h_lo, w2_hi, w2_lo, b_hc,
                                              nullptr, nullptr, c,
                                              BATCH, CNV_DIM, HID_DIM);
    }

    // 4) fused double conv1d(k2,s2) + tanh
    {
        int total = BATCH * OUT_DIM;
        conv_fused<<<(total + 255) / 256, 256>>>(c, w_c1, b_c1, w_c2, b_c2, out);
    }
}

// round 6
// speedup vs baseline: 2.8281x; 1.2873x over previous
#include <cuda_runtime.h>
#include <cuda_fp16.h>
#include <math.h>
#include <stdint.h>

// ---------------------------------------------------------------------------
// MPWEncoder via mma.sync — fp16 2-term scheme:
//   A (activations) kept EXACT as fp16 hi+lo; B (weights) rounded to fp16.
//   acc += Ah*B + Al*B   (fp32 accumulators; only error = w fp16 rounding)
// Dims: BATCH=16384, IN=4096, HID=2048, CNV1=1024, out [16384, 256]
// ---------------------------------------------------------------------------
#define BATCH   16384
#define IN_DIM  4096
#define HID_DIM 2048
#define CNV_DIM 1024
#define OUT_DIM 256

typedef __half f16;

// ------------------------- device scratch (no allocs) ----------------------
__device__ __align__(1024) f16 g_x_hi[(size_t)BATCH * IN_DIM];
__device__ __align__(1024) f16 g_x_lo[(size_t)BATCH * IN_DIM];
__device__ __align__(1024) f16 g_w1  [(size_t)HID_DIM * IN_DIM];
__device__ __align__(1024) f16 g_h_hi[(size_t)BATCH * HID_DIM];
__device__ __align__(1024) f16 g_h_lo[(size_t)BATCH * HID_DIM];
__device__ __align__(1024) f16 g_w2  [(size_t)CNV_DIM * HID_DIM];
__device__ __align__(1024) float g_c [(size_t)BATCH * CNV_DIM];
__device__ int g_mask_mode[2];

// ------------------------- PTX helpers -------------------------------------
__device__ __forceinline__ uint32_t smem_u32(const void* p) {
    uint32_t a;
    asm("{ .reg .u64 t; cvta.to.shared.u64 t, %1; cvt.u32.u64 %0, t; }"
        : "=r"(a) : "l"(p));
    return a;
}
__device__ __forceinline__ void cp16(uint32_t dst, const void* src) {
    asm volatile("cp.async.cg.shared.global [%0], [%1], 16;" :: "r"(dst), "l"(src));
}
__device__ __forceinline__ void cp_commit() {
    asm volatile("cp.async.commit_group;" ::: "memory");
}
template <int N>
__device__ __forceinline__ void cp_wait() {
    asm volatile("cp.async.wait_group %0;" :: "n"(N) : "memory");
}
__device__ __forceinline__ void ldsm_x4(uint32_t addr, uint32_t* r) {
    asm volatile("ldmatrix.sync.aligned.m8n8.x4.shared.b16 {%0,%1,%2,%3}, [%4];"
                 : "=r"(r[0]), "=r"(r[1]), "=r"(r[2]), "=r"(r[3]) : "r"(addr));
}
__device__ __forceinline__ void mma16816(float* c, const uint32_t* a, const uint32_t* b) {
    asm volatile(
        "mma.sync.aligned.m16n8k16.row.col.f32.f16.f16.f32 "
        "{%0,%1,%2,%3}, {%4,%5,%6,%7}, {%8,%9}, {%0,%1,%2,%3};"
        : "+f"(c[0]), "+f"(c[1]), "+f"(c[2]), "+f"(c[3])
        : "r"(a[0]), "r"(a[1]), "r"(a[2]), "r"(a[3]), "r"(b[0]), "r"(b[1]));
}

// ------------------------- mask detection + preps ---------------------------
__global__ void detect_mask_mode(const uint32_t* __restrict__ m, int* __restrict__ mode) {
    int floatish = 0, all01 = 1;
    for (int i = 0; i < 256; ++i) {
        uint32_t w = m[i];
        if (w == 0x3F800000u) floatish = 1;
        if (w > 1u) all01 = 0;
    }
    *mode = floatish ? 2 : (all01 ? 1 : 0);
}

__device__ __forceinline__ uint32_t pack_h2(float a, float b) {
    __half2 t = __floats2half2_rn(a, b);
    return *reinterpret_cast<uint32_t*>(&t);
}

// split fp32 -> exact fp16 hi + fp16 lo (lo = rn(v - hi), residual ~2^-22)
__device__ __forceinline__ void split4h(float4 v, uint2& ho, uint2& lo) {
    float h0 = __half2float(__float2half_rn(v.x));
    float h1 = __half2float(__float2half_rn(v.y));
    float h2 = __half2float(__float2half_rn(v.z));
    float h3 = __half2float(__float2half_rn(v.w));
    ho.x = pack_h2(h0, h1);
    ho.y = pack_h2(h2, h3);
    lo.x = pack_h2(v.x - h0, v.y - h1);
    lo.y = pack_h2(v.z - h2, v.w - h3);
}

__global__ void prep_split_x(const float* __restrict__ x,
                             f16* __restrict__ hi, f16* __restrict__ lo, size_t n4) {
    size_t i = (size_t)blockIdx.x * blockDim.x + threadIdx.x;
    if (i >= n4) return;
    float4 v = ((const float4*)x)[i];
    uint2 ho, lv;
    split4h(v, ho, lv);
    ((uint2*)hi)[i] = ho;
    ((uint2*)lo)[i] = lv;
}

// masked weight -> single fp16
__global__ void prep_w_f16(const float* __restrict__ w, const void* __restrict__ mask,
                           const int* __restrict__ mode_p,
                           f16* __restrict__ out, size_t n4) {
    size_t i = (size_t)blockIdx.x * blockDim.x + threadIdx.x;
    if (i >= n4) return;
    const int mode = *mode_p;
    float4 v = ((const float4*)w)[i];
    bool m0, m1, m2, m3;
    if (mode == 0) {
        uchar4 mm = ((const uchar4*)mask)[i];
        m0 = mm.x; m1 = mm.y; m2 = mm.z; m3 = mm.w;
    } else if (mode == 1) {
        int4 mm = ((const int4*)mask)[i];
        m0 = mm.x; m1 = mm.y; m2 = mm.z; m3 = mm.w;
    } else {
        float4 mm = ((const float4*)mask)[i];
        m0 = mm.x != 0.f; m1 = mm.y != 0.f; m2 = mm.z != 0.f; m3 = mm.w != 0.f;
    }
    uint2 o;
    o.x = pack_h2(m0 ? v.x : 0.f, m1 ? v.y : 0.f);
    o.y = pack_h2(m2 ? v.z : 0.f, m3 ? v.w : 0.f);
    ((uint2*)out)[i] = o;
}

// ------------------------- mma.sync GEMM ------------------------------------
// C[M,N] = tanh(A[M,K] @ B[N,K]^T + bias[N]); A as fp16 hi/lo, B single fp16.
// Block tile 256x128x32, 8 warps (64x64 each), 3-stage cp.async pipeline.
#define BMT 256
#define BNT 128
#define BKT 32
#define ROWB 80                            // 64B data + 16B pad per K-slab row
#define A_BYTES (BMT * ROWB)               // 20480 (per A component)
#define B_BYTES (BNT * ROWB)               // 10240
#define STAGE_BYTES (2 * A_BYTES + B_BYTES)  // 51200
#define NSTAGE 3
#define SMEM_GEMM (NSTAGE * STAGE_BYTES)   // 153600

__device__ __forceinline__ void load_stage(uint32_t sb,
                                           const f16* Ah, const f16* Al,
                                           const f16* B,
                                           int m0, int n0, int k0, int K, int tid) {
#pragma unroll
    for (int i = 0; i < 4; ++i) {
        const int ch = tid + (i << 8);
        const int row = ch >> 2, u = ch & 3;
        const uint32_t doff = row * ROWB + ((u ^ (row & 3)) << 4);
        const size_t g = (size_t)(m0 + row) * K + k0 + u * 8;
        cp16(sb + doff, Ah + g);
        cp16(sb + A_BYTES + doff, Al + g);
    }
#pragma unroll
    for (int i = 0; i < 2; ++i) {
        const int ch = tid + (i << 8);
        const int row = ch >> 2, u = ch & 3;
        const uint32_t doff = row * ROWB + ((u ^ (row & 3)) << 4);
        const size_t g = (size_t)(n0 + row) * K + k0 + u * 8;
        cp16(sb + 2 * A_BYTES + doff, B + g);
    }
}

template <int MODE>   // 0: fp16 hi/lo out; 1: fp32 out
__global__ __launch_bounds__(256, 1)
void gemm_mma(const f16* __restrict__ Ah, const f16* __restrict__ Al,
              const f16* __restrict__ B, const float* __restrict__ bias,
              f16* __restrict__ Ch, f16* __restrict__ Cl, float* __restrict__ Cf,
              int M, int N, int K) {
    extern __shared__ __align__(128) char smem[];
    const uint32_t sbase = smem_u32(smem);
    const int tid = threadIdx.x;
    const int wid = tid >> 5;
    const int lane = tid & 31;
    const int warp_m = wid >> 1;
    const int warp_n = wid & 1;
    const int m0 = blockIdx.y * BMT;
    const int n0 = blockIdx.x * BNT;

    float acc[4][8][4];
#pragma unroll
    for (int a = 0; a < 4; ++a)
#pragma unroll
        for (int b = 0; b < 8; ++b)
#pragma unroll
            for (int d = 0; d < 4; ++d) acc[a][b][d] = 0.0f;

    const int aRow = warp_m * 64 + (lane & 7) + (((lane >> 3) & 1) << 3);
    const int aUsel = lane >> 4;
    const int bRow = warp_n * 64 + ((lane >> 4) << 3) + (lane & 7);
    const int bUsel = (lane >> 3) & 1;

    const int T = K / BKT;
    // prologue: fill stages 0 and 1
    load_stage(sbase, Ah, Al, B, m0, n0, 0, K, tid);
    cp_commit();
    load_stage(sbase + STAGE_BYTES, Ah, Al, B, m0, n0, BKT, K, tid);
    cp_commit();

    int stg_idx = 0;
    for (int t = 0; t < T; ++t) {
        if (t + 2 < T) {
            int li = stg_idx + 2;
            if (li >= NSTAGE) li -= NSTAGE;
            load_stage(sbase + li * STAGE_BYTES, Ah, Al, B, m0, n0, (t + 2) * BKT, K, tid);
            cp_commit();
            cp_wait<2>();
        } else if (t + 1 < T) {
            cp_wait<1>();
        } else {
            cp_wait<0>();
        }
        __syncthreads();

        const uint32_t stg = sbase + stg_idx * STAGE_BYTES;
        const uint32_t aHiB = stg, aLoB = stg + A_BYTES;
        const uint32_t bB = stg + 2 * A_BYTES;

#pragma unroll
        for (int kk = 0; kk < 2; ++kk) {
            uint32_t ah[4][4], al[4][4];
#pragma unroll
            for (int mf = 0; mf < 4; ++mf) {
                const int m = aRow + mf * 16;
                const int u = kk * 2 + aUsel;
                const uint32_t off = m * ROWB + ((u ^ (m & 3)) << 4);
                ldsm_x4(aHiB + off, ah[mf]);
                ldsm_x4(aLoB + off, al[mf]);
            }
#pragma unroll
            for (int nfp = 0; nfp < 4; ++nfp) {
                const int n = bRow + nfp * 16;
                const int u = kk * 2 + bUsel;
                const uint32_t off = n * ROWB + ((u ^ (n & 3)) << 4);
                uint32_t bh[4];
                ldsm_x4(bB + off, bh);   // [n][k] tile == col-major B, non-trans
#pragma unroll
                for (int mf = 0; mf < 4; ++mf) {
                    mma16816(acc[mf][2 * nfp],     ah[mf], bh);
                    mma16816(acc[mf][2 * nfp],     al[mf], bh);
                    mma16816(acc[mf][2 * nfp + 1], ah[mf], bh + 2);
                    mma16816(acc[mf][2 * nfp + 1], al[mf], bh + 2);
                }
            }
        }
        __syncthreads();
        if (++stg_idx == NSTAGE) stg_idx = 0;
    }

    // ----------------- epilogue: bias + tanh + store -----------------------
    const int gid = lane >> 2, tg = lane & 3;
#pragma unroll
    for (int mf = 0; mf < 4; ++mf) {
#pragma unroll
        for (int nf = 0; nf < 8; ++nf) {
            const int row0 = m0 + warp_m * 64 + mf * 16 + gid;
            const int col = n0 + warp_n * 64 + nf * 8 + tg * 2;
            const float bv0 = bias[col], bv1 = bias[col + 1];
            const float* a4 = acc[mf][nf];
            const float v00 = tanhf(a4[0] + bv0);
            const float v01 = tanhf(a4[1] + bv1);
            const float v10 = tanhf(a4[2] + bv0);
            const float v11 = tanhf(a4[3] + bv1);
            if (MODE == 0) {
                const float h00 = __half2float(__float2half_rn(v00));
                const float h01 = __half2float(__float2half_rn(v01));
                const float h10 = __half2float(__float2half_rn(v10));
                const float h11 = __half2float(__float2half_rn(v11));
                uint32_t* ChW = (uint32_t*)Ch;
                uint32_t* ClW = (uint32_t*)Cl;
                const size_t w0 = (size_t)row0 * (N >> 1) + (col >> 1);
                const size_t w1 = (size_t)(row0 + 8) * (N >> 1) + (col >> 1);
                ChW[w0] = pack_h2(h00, h01);
                ClW[w0] = pack_h2(v00 - h00, v01 - h01);
                ChW[w1] = pack_h2(h10, h11);
                ClW[w1] = pack_h2(v10 - h10, v11 - h11);
            } else {
                float2* p0 = (float2*)(Cf + (size_t)row0 * N + col);
                float2* p1 = (float2*)(Cf + (size_t)(row0 + 8) * N + col);
                *p0 = make_float2(v00, v01);
                *p1 = make_float2(v10, v11);
            }
        }
    }
}

// ------------------------- fused double conv --------------------------------
__global__ void conv_fused(const float* __restrict__ c,
                           const float* __restrict__ wc1, const float* __restrict__ bc1,
                           const float* __restrict__ wc2, const float* __restrict__ bc2,
                           float* __restrict__ out) {
    int idx = blockIdx.x * blockDim.x + threadIdx.x;
    if (idx >= BATCH * OUT_DIM) return;
    const float w10 = wc1[0], w11 = wc1[1];
    const float w20 = wc2[0], w21 = wc2[1];
    const float b1 = bc1[0], b2 = bc2[0];
    float4 v = ((const float4*)c)[idx];
    float t1 = tanhf(fmaf(v.x, w10, fmaf(v.y, w11, b1)));
    float t2 = tanhf(fmaf(v.z, w10, fmaf(v.w, w11, b1)));
    out[idx] = tanhf(fmaf(t1, w20, fmaf(t2, w21, b2)));
}

// ------------------------- launch ------------------------------------------
extern "C" void kernel_launch(void* const* d_in, const int* in_sizes, int n_in,
                              void* d_out, int out_size) {
    const float* x       = (const float*)d_in[0];
    const void*  mask_ih = d_in[1];
    const void*  mask_hc = d_in[2];
    const float* w_ih    = (const float*)d_in[3];
    const float* b_ih    = (const float*)d_in[4];
    const float* w_hc    = (const float*)d_in[5];
    const float* b_hc    = (const float*)d_in[6];
    const float* w_c1    = (const float*)d_in[7];
    const float* b_c1    = (const float*)d_in[8];
    const float* w_c2    = (const float*)d_in[9];
    const float* b_c2    = (const float*)d_in[10];
    float* out = (float*)d_out;

    f16 *x_hi, *x_lo, *w1, *h_hi, *h_lo, *w2;
    float* c;
    int* mode;
    cudaGetSymbolAddress((void**)&x_hi, g_x_hi);
    cudaGetSymbolAddress((void**)&x_lo, g_x_lo);
    cudaGetSymbolAddress((void**)&w1, g_w1);
    cudaGetSymbolAddress((void**)&h_hi, g_h_hi);
    cudaGetSymbolAddress((void**)&h_lo, g_h_lo);
    cudaGetSymbolAddress((void**)&w2, g_w2);
    cudaGetSymbolAddress((void**)&c, g_c);
    cudaGetSymbolAddress((void**)&mode, g_mask_mode);

    cudaFuncSetAttribute(gemm_mma<0>, cudaFuncAttributeMaxDynamicSharedMemorySize, SMEM_GEMM);
    cudaFuncSetAttribute(gemm_mma<1>, cudaFuncAttributeMaxDynamicSharedMemorySize, SMEM_GEMM);

    // 0) mask dtype detection
    detect_mask_mode<<<1, 1>>>((const uint32_t*)mask_ih, mode + 0);
    detect_mask_mode<<<1, 1>>>((const uint32_t*)mask_hc, mode + 1);

    // 1) preps: x -> fp16 hi/lo; masked w1/w2 -> fp16
    {
        size_t n4 = (size_t)BATCH * IN_DIM / 4;
        prep_split_x<<<(unsigned)((n4 + 255) / 256), 256>>>(x, x_hi, x_lo, n4);
    }
    {
        size_t n4 = (size_t)HID_DIM * IN_DIM / 4;
        prep_w_f16<<<(unsigned)((n4 + 255) / 256), 256>>>(w_ih, mask_ih, mode + 0, w1, n4);
    }
    {
        size_t n4 = (size_t)CNV_DIM * HID_DIM / 4;
        prep_w_f16<<<(unsigned)((n4 + 255) / 256), 256>>>(w_hc, mask_hc, mode + 1, w2, n4);
    }

    // 2) h = tanh(x @ w1^T + b_ih) -> fp16 hi/lo
    {
        dim3 grid(HID_DIM / BNT, BATCH / BMT);   // (16, 64)
        gemm_mma<0><<<grid, 256, SMEM_GEMM>>>(x_hi, x_lo, w1, b_ih,
                                              h_hi, h_lo, nullptr,
                                              BATCH, HID_DIM, IN_DIM);
    }

    // 3) c = tanh(h @ w2^T + b_hc) -> fp32
    {
        dim3 grid(CNV_DIM / BNT, BATCH / BMT);   // (8, 64)
        gemm_mma<1><<<grid, 256, SMEM_GEMM>>>(h_hi, h_lo, w2, b_hc,
                                              nullptr, nullptr, c,
                                              BATCH, CNV_DIM, HID_DIM);
    }

    // 4) fused double conv1d(k2,s2) + tanh
    {
        int total = BATCH * OUT_DIM;
        conv_fused<<<(total + 255) / 256, 256>>>(c, w_c1, b_c1, w_c2, b_c2, out);
    }
}

// round 7
// speedup vs baseline: 4.3250x; 1.5293x over previous
#include <cuda_runtime.h>
#include <cuda_fp16.h>
#include <math.h>
#include <stdint.h>

// ---------------------------------------------------------------------------
// MPWEncoder via mma.sync — plain fp16 GEMMs (fp32 accum), both operands
// rounded to fp16 (error budget measured: one rounding source -> 2.67e-4;
// two sources ~3.8e-4 < 1e-3). 4-stage cp.async pipeline, 1 barrier/tile.
// Dims: BATCH=16384, IN=4096, HID=2048, CNV1=1024, out [16384, 256]
// ---------------------------------------------------------------------------
#define BATCH   16384
#define IN_DIM  4096
#define HID_DIM 2048
#define CNV_DIM 1024
#define OUT_DIM 256

typedef __half f16;

// ------------------------- device scratch (no allocs) ----------------------
__device__ __align__(1024) f16 g_x [(size_t)BATCH * IN_DIM];
__device__ __align__(1024) f16 g_w1[(size_t)HID_DIM * IN_DIM];
__device__ __align__(1024) f16 g_h [(size_t)BATCH * HID_DIM];
__device__ __align__(1024) f16 g_w2[(size_t)CNV_DIM * HID_DIM];
__device__ __align__(1024) float g_c[(size_t)BATCH * CNV_DIM];
__device__ int g_mask_mode[2];

// ------------------------- PTX helpers -------------------------------------
__device__ __forceinline__ uint32_t smem_u32(const void* p) {
    uint32_t a;
    asm("{ .reg .u64 t; cvta.to.shared.u64 t, %1; cvt.u32.u64 %0, t; }"
        : "=r"(a) : "l"(p));
    return a;
}
__device__ __forceinline__ void cp16(uint32_t dst, const void* src) {
    asm volatile("cp.async.cg.shared.global [%0], [%1], 16;" :: "r"(dst), "l"(src));
}
__device__ __forceinline__ void cp_commit() {
    asm volatile("cp.async.commit_group;" ::: "memory");
}
template <int N>
__device__ __forceinline__ void cp_wait() {
    asm volatile("cp.async.wait_group %0;" :: "n"(N) : "memory");
}
__device__ __forceinline__ void ldsm_x4(uint32_t addr, uint32_t* r) {
    asm volatile("ldmatrix.sync.aligned.m8n8.x4.shared.b16 {%0,%1,%2,%3}, [%4];"
                 : "=r"(r[0]), "=r"(r[1]), "=r"(r[2]), "=r"(r[3]) : "r"(addr));
}
__device__ __forceinline__ void mma16816(float* c, const uint32_t* a, const uint32_t* b) {
    asm volatile(
        "mma.sync.aligned.m16n8k16.row.col.f32.f16.f16.f32 "
        "{%0,%1,%2,%3}, {%4,%5,%6,%7}, {%8,%9}, {%0,%1,%2,%3};"
        : "+f"(c[0]), "+f"(c[1]), "+f"(c[2]), "+f"(c[3])
        : "r"(a[0]), "r"(a[1]), "r"(a[2]), "r"(a[3]), "r"(b[0]), "r"(b[1]));
}

// ------------------------- mask detection + preps ---------------------------
__global__ void detect_mask_mode(const uint32_t* __restrict__ m, int* __restrict__ mode) {
    int floatish = 0, all01 = 1;
    for (int i = 0; i < 256; ++i) {
        uint32_t w = m[i];
        if (w == 0x3F800000u) floatish = 1;
        if (w > 1u) all01 = 0;
    }
    *mode = floatish ? 2 : (all01 ? 1 : 0);
}

__device__ __forceinline__ uint32_t pack_h2(float a, float b) {
    __half2 t = __floats2half2_rn(a, b);
    return *reinterpret_cast<uint32_t*>(&t);
}

__global__ void prep_x_f16(const float* __restrict__ x, f16* __restrict__ out, size_t n4) {
    size_t i = (size_t)blockIdx.x * blockDim.x + threadIdx.x;
    if (i >= n4) return;
    float4 v = ((const float4*)x)[i];
    uint2 o;
    o.x = pack_h2(v.x, v.y);
    o.y = pack_h2(v.z, v.w);
    ((uint2*)out)[i] = o;
}

__global__ void prep_w_f16(const float* __restrict__ w, const void* __restrict__ mask,
                           const int* __restrict__ mode_p,
                           f16* __restrict__ out, size_t n4) {
    size_t i = (size_t)blockIdx.x * blockDim.x + threadIdx.x;
    if (i >= n4) return;
    const int mode = *mode_p;
    float4 v = ((const float4*)w)[i];
    bool m0, m1, m2, m3;
    if (mode == 0) {
        uchar4 mm = ((const uchar4*)mask)[i];
        m0 = mm.x; m1 = mm.y; m2 = mm.z; m3 = mm.w;
    } else if (mode == 1) {
        int4 mm = ((const int4*)mask)[i];
        m0 = mm.x; m1 = mm.y; m2 = mm.z; m3 = mm.w;
    } else {
        float4 mm = ((const float4*)mask)[i];
        m0 = mm.x != 0.f; m1 = mm.y != 0.f; m2 = mm.z != 0.f; m3 = mm.w != 0.f;
    }
    uint2 o;
    o.x = pack_h2(m0 ? v.x : 0.f, m1 ? v.y : 0.f);
    o.y = pack_h2(m2 ? v.z : 0.f, m3 ? v.w : 0.f);
    ((uint2*)out)[i] = o;
}

// ------------------------- mma.sync GEMM ------------------------------------
// C[M,N] = tanh(A[M,K] @ B[N,K]^T + bias[N]); A,B fp16, fp32 accumulate.
// Block tile 256x128x32, 8 warps (64x64 each), 4-stage cp.async pipeline,
// a single __syncthreads per k-tile (loads for t+3 issued after barrier t,
// so the reused buffer (t-1)%4 is provably drained).
#define BMT 256
#define BNT 128
#define BKT 32
#define ROWB 80                            // 64B data + 16B pad per K-slab row
#define A_BYTES (BMT * ROWB)               // 20480
#define B_BYTES (BNT * ROWB)               // 10240
#define STAGE_BYTES (A_BYTES + B_BYTES)    // 30720
#define NSTAGE 4
#define SMEM_GEMM (NSTAGE * STAGE_BYTES)   // 122880

__device__ __forceinline__ void load_stage(uint32_t sb,
                                           const f16* A, const f16* B,
                                           int m0, int n0, int k0, int K, int tid) {
#pragma unroll
    for (int i = 0; i < 4; ++i) {
        const int ch = tid + (i << 8);
        const int row = ch >> 2, u = ch & 3;
        const uint32_t doff = row * ROWB + ((u ^ (row & 3)) << 4);
        cp16(sb + doff, A + (size_t)(m0 + row) * K + k0 + u * 8);
    }
#pragma unroll
    for (int i = 0; i < 2; ++i) {
        const int ch = tid + (i << 8);
        const int row = ch >> 2, u = ch & 3;
        const uint32_t doff = row * ROWB + ((u ^ (row & 3)) << 4);
        cp16(sb + A_BYTES + doff, B + (size_t)(n0 + row) * K + k0 + u * 8);
    }
}

template <int MODE>   // 0: fp16 out; 1: fp32 out
__global__ __launch_bounds__(256, 1)
void gemm_mma(const f16* __restrict__ A, const f16* __restrict__ B,
              const float* __restrict__ bias,
              f16* __restrict__ Ch, float* __restrict__ Cf,
              int M, int N, int K) {
    extern __shared__ __align__(128) char smem[];
    const uint32_t sbase = smem_u32(smem);
    const int tid = threadIdx.x;
    const int wid = tid >> 5;
    const int lane = tid & 31;
    const int warp_m = wid >> 1;
    const int warp_n = wid & 1;
    const int m0 = blockIdx.y * BMT;
    const int n0 = blockIdx.x * BNT;

    float acc[4][8][4];
#pragma unroll
    for (int a = 0; a < 4; ++a)
#pragma unroll
        for (int b = 0; b < 8; ++b)
#pragma unroll
            for (int d = 0; d < 4; ++d) acc[a][b][d] = 0.0f;

    const int aRow = warp_m * 64 + (lane & 7) + (((lane >> 3) & 1) << 3);
    const int aUsel = lane >> 4;
    const int bRow = warp_n * 64 + ((lane >> 4) << 3) + (lane & 7);
    const int bUsel = (lane >> 3) & 1;

    const int T = K / BKT;
    // prologue: fill stages 0..2
    load_stage(sbase, A, B, m0, n0, 0, K, tid);
    cp_commit();
    load_stage(sbase + STAGE_BYTES, A, B, m0, n0, BKT, K, tid);
    cp_commit();
    load_stage(sbase + 2 * STAGE_BYTES, A, B, m0, n0, 2 * BKT, K, tid);
    cp_commit();

    for (int t = 0; t < T; ++t) {
        // wait for stage t (outstanding groups allowed = min(2, T-1-t))
        if (t + 2 < T)      cp_wait<2>();
        else if (t + 1 < T) cp_wait<1>();
        else                cp_wait<0>();
        __syncthreads();   // the ONLY barrier per tile

        // issue loads for stage t+3 (buffer (t+3)&3 == (t-1)&3, drained above)
        if (t + 3 < T) {
            load_stage(sbase + ((t + 3) & 3) * STAGE_BYTES, A, B,
                       m0, n0, (t + 3) * BKT, K, tid);
            cp_commit();
        }

        const uint32_t stg = sbase + (t & 3) * STAGE_BYTES;
        const uint32_t aB = stg, bB = stg + A_BYTES;

#pragma unroll
        for (int kk = 0; kk < 2; ++kk) {
            uint32_t ah[4][4];
#pragma unroll
            for (int mf = 0; mf < 4; ++mf) {
                const int m = aRow + mf * 16;
                const int u = kk * 2 + aUsel;
                const uint32_t off = m * ROWB + ((u ^ (m & 3)) << 4);
                ldsm_x4(aB + off, ah[mf]);
            }
#pragma unroll
            for (int nfp = 0; nfp < 4; ++nfp) {
                const int n = bRow + nfp * 16;
                const int u = kk * 2 + bUsel;
                const uint32_t off = n * ROWB + ((u ^ (n & 3)) << 4);
                uint32_t bh[4];
                ldsm_x4(bB + off, bh);   // [n][k] tile == col-major B, non-trans
#pragma unroll
                for (int mf = 0; mf < 4; ++mf) {
                    mma16816(acc[mf][2 * nfp],     ah[mf], bh);
                    mma16816(acc[mf][2 * nfp + 1], ah[mf], bh + 2);
                }
            }
        }
    }

    // ----------------- epilogue: bias + tanh + store -----------------------
    const int gid = lane >> 2, tg = lane & 3;
#pragma unroll
    for (int mf = 0; mf < 4; ++mf) {
#pragma unroll
        for (int nf = 0; nf < 8; ++nf) {
            const int row0 = m0 + warp_m * 64 + mf * 16 + gid;
            const int col = n0 + warp_n * 64 + nf * 8 + tg * 2;
            const float bv0 = bias[col], bv1 = bias[col + 1];
            const float* a4 = acc[mf][nf];
            const float v00 = tanhf(a4[0] + bv0);
            const float v01 = tanhf(a4[1] + bv1);
            const float v10 = tanhf(a4[2] + bv0);
            const float v11 = tanhf(a4[3] + bv1);
            if (MODE == 0) {
                uint32_t* ChW = (uint32_t*)Ch;
                ChW[(size_t)row0 * (N >> 1) + (col >> 1)]       = pack_h2(v00, v01);
                ChW[(size_t)(row0 + 8) * (N >> 1) + (col >> 1)] = pack_h2(v10, v11);
            } else {
                *(float2*)(Cf + (size_t)row0 * N + col)       = make_float2(v00, v01);
                *(float2*)(Cf + (size_t)(row0 + 8) * N + col) = make_float2(v10, v11);
            }
        }
    }
}

// ------------------------- fused double conv --------------------------------
__global__ void conv_fused(const float* __restrict__ c,
                           const float* __restrict__ wc1, const float* __restrict__ bc1,
                           const float* __restrict__ wc2, const float* __restrict__ bc2,
                           float* __restrict__ out) {
    int idx = blockIdx.x * blockDim.x + threadIdx.x;
    if (idx >= BATCH * OUT_DIM) return;
    const float w10 = wc1[0], w11 = wc1[1];
    const float w20 = wc2[0], w21 = wc2[1];
    const float b1 = bc1[0], b2 = bc2[0];
    float4 v = ((const float4*)c)[idx];
    float t1 = tanhf(fmaf(v.x, w10, fmaf(v.y, w11, b1)));
    float t2 = tanhf(fmaf(v.z, w10, fmaf(v.w, w11, b1)));
    out[idx] = tanhf(fmaf(t1, w20, fmaf(t2, w21, b2)));
}

// ------------------------- launch ------------------------------------------
extern "C" void kernel_launch(void* const* d_in, const int* in_sizes, int n_in,
                              void* d_out, int out_size) {
    const float* x       = (const float*)d_in[0];
    const void*  mask_ih = d_in[1];
    const void*  mask_hc = d_in[2];
    const float* w_ih    = (const float*)d_in[3];
    const float* b_ih    = (const float*)d_in[4];
    const float* w_hc    = (const float*)d_in[5];
    const float* b_hc    = (const float*)d_in[6];
    const float* w_c1    = (const float*)d_in[7];
    const float* b_c1    = (const float*)d_in[8];
    const float* w_c2    = (const float*)d_in[9];
    const float* b_c2    = (const float*)d_in[10];
    float* out = (float*)d_out;

    f16 *xh, *w1, *h, *w2;
    float* c;
    int* mode;
    cudaGetSymbolAddress((void**)&xh, g_x);
    cudaGetSymbolAddress((void**)&w1, g_w1);
    cudaGetSymbolAddress((void**)&h, g_h);
    cudaGetSymbolAddress((void**)&w2, g_w2);
    cudaGetSymbolAddress((void**)&c, g_c);
    cudaGetSymbolAddress((void**)&mode, g_mask_mode);

    cudaFuncSetAttribute(gemm_mma<0>, cudaFuncAttributeMaxDynamicSharedMemorySize, SMEM_GEMM);
    cudaFuncSetAttribute(gemm_mma<1>, cudaFuncAttributeMaxDynamicSharedMemorySize, SMEM_GEMM);

    // 0) mask dtype detection
    detect_mask_mode<<<1, 1>>>((const uint32_t*)mask_ih, mode + 0);
    detect_mask_mode<<<1, 1>>>((const uint32_t*)mask_hc, mode + 1);

    // 1) preps: x -> fp16; masked w1/w2 -> fp16
    {
        size_t n4 = (size_t)BATCH * IN_DIM / 4;
        prep_x_f16<<<(unsigned)((n4 + 255) / 256), 256>>>(x, xh, n4);
    }
    {
        size_t n4 = (size_t)HID_DIM * IN_DIM / 4;
        prep_w_f16<<<(unsigned)((n4 + 255) / 256), 256>>>(w_ih, mask_ih, mode + 0, w1, n4);
    }
    {
        size_t n4 = (size_t)CNV_DIM * HID_DIM / 4;
        prep_w_f16<<<(unsigned)((n4 + 255) / 256), 256>>>(w_hc, mask_hc, mode + 1, w2, n4);
    }

    // 2) h = tanh(x @ w1^T + b_ih) -> fp16
    {
        dim3 grid(HID_DIM / BNT, BATCH / BMT);   // (16, 64)
        gemm_mma<0><<<grid, 256, SMEM_GEMM>>>(xh, w1, b_ih, h, nullptr,
                                              BATCH, HID_DIM, IN_DIM);
    }

    // 3) c = tanh(h @ w2^T + b_hc) -> fp32
    {
        dim3 grid(CNV_DIM / BNT, BATCH / BMT);   // (8, 64)
        gemm_mma<1><<<grid, 256, SMEM_GEMM>>>(h, w2, b_hc, nullptr, c,
                                              BATCH, CNV_DIM, HID_DIM);
    }

    // 4) fused double conv1d(k2,s2) + tanh
    {
        int total = BATCH * OUT_DIM;
        conv_fused<<<(total + 255) / 256, 256>>>(c, w_c1, b_c1, w_c2, b_c2, out);
    }
}